// round 16
// baseline (speedup 1.0000x reference)
#include <cuda_runtime.h>
#include <cuda_bf16.h>
#include <cuda_fp16.h>
#include <math.h>
#include <stdint.h>

// ---------------------------------------------------------------------------
// Problem constants
// ---------------------------------------------------------------------------
#define BATCH 64
#define TLEN  1024
#define NF    512
#define NH    512
#define NK    500
#define NKP   512              // padded chain count (pow2 for scan)
#define MROWS (BATCH * TLEN)   // 65536

// GEMM config
#define BM 64
#define BN 256
#define BK 32
#define KCHUNKS (NF / BK)      // 16
#define STAGES 4

#define A32_PITCH_B 144
#define A32_ST_BYTES (BM * A32_PITCH_B)      // 9216
#define B_ST_BYTES (BK * BN * 2)             // 16384
#define ST_BYTES (A32_ST_BYTES + B_ST_BYTES) // 25600
#define A16_PITCH 40
#define A16_BUF_BYTES (BM * A16_PITCH * 2)   // 5120
#define A16_OFF (STAGES * ST_BYTES)          // 102400
#define DYN_SMEM (A16_OFF + 2 * A16_BUF_BYTES) // 112640

#define VIS_FAST 8             // full-prefetch tier
#define VIS_CAP 24             // register-cache tier

// ---------------------------------------------------------------------------
// Device scratch
// ---------------------------------------------------------------------------
__device__ __align__(16) __half g_B[(size_t)NF * NH];
__device__ float g_po[(size_t)MROWS * 2 * 2];
__device__ int      g_vstart[BATCH * (NKP + 1)];
__device__ uint32_t g_visits[BATCH * TLEN];

// ---------------------------------------------------------------------------
// PTX helpers
// ---------------------------------------------------------------------------
__device__ __forceinline__ uint32_t smem_u32(const void* p) {
    uint32_t a;
    asm("{ .reg .u64 t; cvta.to.shared.u64 t, %1; cvt.u32.u64 %0, t; }" : "=r"(a) : "l"(p));
    return a;
}
__device__ __forceinline__ void cpa16(uint32_t dst, const void* src) {
    asm volatile("cp.async.cg.shared.global [%0], [%1], 16;" :: "r"(dst), "l"(src));
}
__device__ __forceinline__ void cp_commit() {
    asm volatile("cp.async.commit_group;" ::: "memory");
}
__device__ __forceinline__ void cp_wait1() {
    asm volatile("cp.async.wait_group 1;" ::: "memory");
}
__device__ __forceinline__ void cp_wait2() {
    asm volatile("cp.async.wait_group 2;" ::: "memory");
}
__device__ __forceinline__ void lds128(float4& v, uint32_t addr) {
    asm volatile("ld.shared.v4.f32 {%0,%1,%2,%3}, [%4];"
                 : "=f"(v.x), "=f"(v.y), "=f"(v.z), "=f"(v.w) : "r"(addr));
}
__device__ __forceinline__ void sts128(uint32_t addr, uint32_t r0, uint32_t r1,
                                       uint32_t r2, uint32_t r3) {
    asm volatile("st.shared.v4.b32 [%0], {%1,%2,%3,%4};"
                 :: "r"(addr), "r"(r0), "r"(r1), "r"(r2), "r"(r3) : "memory");
}
__device__ __forceinline__ void ldm_x4(uint32_t r[4], uint32_t addr) {
    asm volatile("ldmatrix.sync.aligned.m8n8.x4.shared.b16 {%0,%1,%2,%3}, [%4];"
                 : "=r"(r[0]), "=r"(r[1]), "=r"(r[2]), "=r"(r[3]) : "r"(addr));
}
__device__ __forceinline__ void ldm_x4_t(uint32_t& r0, uint32_t& r1, uint32_t& r2,
                                         uint32_t& r3, uint32_t addr) {
    asm volatile("ldmatrix.sync.aligned.m8n8.x4.trans.shared.b16 {%0,%1,%2,%3}, [%4];"
                 : "=r"(r0), "=r"(r1), "=r"(r2), "=r"(r3) : "r"(addr));
}
__device__ __forceinline__ void mma_fp16(float c[4], const uint32_t a[4], const uint32_t b[2]) {
    asm volatile(
        "mma.sync.aligned.m16n8k16.row.col.f32.f16.f16.f32 "
        "{%0,%1,%2,%3}, {%4,%5,%6,%7}, {%8,%9}, {%0,%1,%2,%3};"
        : "+f"(c[0]), "+f"(c[1]), "+f"(c[2]), "+f"(c[3])
        : "r"(a[0]), "r"(a[1]), "r"(a[2]), "r"(a[3]), "r"(b[0]), "r"(b[1]));
}
__device__ __forceinline__ uint32_t half2_bits(__half2 v) {
    return *(uint32_t*)&v;
}
__device__ __forceinline__ float ftanh(float x) {
    float e = __expf(2.0f * x);
    return 1.0f - __fdividef(2.0f, e + 1.0f);
}

// ---------------------------------------------------------------------------
// Fused prep: blocks [0,BATCH) build visit lists; blocks [BATCH,BATCH+128)
// convert W1 fp32 -> fp16.
// ---------------------------------------------------------------------------
__global__ __launch_bounds__(512)
void prep_kernel(const float* __restrict__ W1,
                 const int* __restrict__ corr, const int* __restrict__ kc)
{
    __shared__ int cnt[NKP];
    __shared__ int scan_buf[NKP];
    __shared__ int pos[NKP];
    const int tid = threadIdx.x;

    if (blockIdx.x >= BATCH) {
        // W1 conversion: 128 blocks x 512 threads x 1 quad
        size_t i = ((size_t)(blockIdx.x - BATCH) * 512 + tid) * 4;
        float4 v = *(const float4*)(W1 + i);
        *(__half2*)(g_B + i)     = __floats2half2_rn(v.x, v.y);
        *(__half2*)(g_B + i + 2) = __floats2half2_rn(v.z, v.w);
        return;
    }

    const int b = blockIdx.x;
    cnt[tid] = 0;
    __syncthreads();

#pragma unroll
    for (int h = 0; h < 2; ++h) {
        int t = tid + h * 512;
        atomicAdd(&cnt[kc[b * TLEN + t]], 1);
    }
    __syncthreads();

    int v = cnt[tid];
    scan_buf[tid] = v;
    __syncthreads();
#pragma unroll
    for (int off = 1; off < NKP; off <<= 1) {
        int add = (tid >= off) ? scan_buf[tid - off] : 0;
        __syncthreads();
        scan_buf[tid] += add;
        __syncthreads();
    }
    int start = scan_buf[tid] - v;
    pos[tid] = start;
    g_vstart[b * (NKP + 1) + tid] = start;
    if (tid == NKP - 1) g_vstart[b * (NKP + 1) + NKP] = TLEN;
    __syncthreads();

#pragma unroll
    for (int h = 0; h < 2; ++h) {
        int t = tid + h * 512;
        int c = kc[b * TLEN + t];
        int slot = atomicAdd(&pos[c], 1);
        g_visits[b * TLEN + slot] = ((uint32_t)t << 1) | (uint32_t)corr[b * TLEN + t];
    }
}

// ---------------------------------------------------------------------------
// GEMM (unchanged from R15)
// ---------------------------------------------------------------------------
extern __shared__ unsigned char dynsmem[];

__device__ __forceinline__ void load_stage(int st, int kcc, int mt, int nt,
                                           const float* __restrict__ FM,
                                           uint32_t smbase, int tid)
{
    const int k0 = kcc * BK;
    const float*  As = FM + (size_t)mt * BM * NF + k0;
    const __half* Bs = g_B + (size_t)k0 * NH + nt * BN;
    const uint32_t sa = smbase + st * ST_BYTES;
    const uint32_t sb = sa + A32_ST_BYTES;
#pragma unroll
    for (int h = 0; h < 2; ++h) {
        int id  = tid + h * 256;
        int row = id >> 3;
        int cq  = id & 7;
        cpa16(sa + (uint32_t)row * A32_PITCH_B + cq * 16,
              As + (size_t)row * NF + cq * 4);
    }
#pragma unroll
    for (int h = 0; h < 4; ++h) {
        int id = tid + h * 256;
        int k  = id >> 5;
        int cb = id & 31;
        cpa16(sb + ((uint32_t)k * 32 + (uint32_t)(cb ^ (k & 7))) * 16,
              Bs + (size_t)k * NH + cb * 8);
    }
}

__global__ __launch_bounds__(256, 2)
void gemm_hmma(const float* __restrict__ FM,
               const float* __restrict__ b1, const float* __restrict__ W2)
{
    const int tid    = threadIdx.x;
    const int lane   = tid & 31;
    const int wid    = tid >> 5;
    const int warp_m = wid & 1;
    const int warp_n = wid >> 1;
    const int nt     = blockIdx.x;
    const int mt     = blockIdx.y;
    const uint32_t smbase = smem_u32(dynsmem);

    const int crow = tid & 63;
    const int cqp  = tid >> 6;
    const uint32_t conv_lds = smbase + (uint32_t)crow * A32_PITCH_B + cqp * 32;
    const uint32_t conv_sts = smbase + A16_OFF + (uint32_t)crow * (A16_PITCH * 2) + cqp * 16;

    float c[2][8][4];
#pragma unroll
    for (int i = 0; i < 2; ++i)
#pragma unroll
        for (int j = 0; j < 8; ++j)
#pragma unroll
            for (int r = 0; r < 4; ++r) c[i][j][r] = 0.f;

#pragma unroll
    for (int s = 0; s < STAGES - 1; ++s) {
        load_stage(s, s, mt, nt, FM, smbase, tid);
        cp_commit();
    }
    cp_wait2();
    __syncthreads();
    {
        float4 v0, v1;
        lds128(v0, conv_lds);
        lds128(v1, conv_lds + 16);
        uint32_t h0 = half2_bits(__floats2half2_rn(v0.x, v0.y));
        uint32_t h1 = half2_bits(__floats2half2_rn(v0.z, v0.w));
        uint32_t h2 = half2_bits(__floats2half2_rn(v1.x, v1.y));
        uint32_t h3 = half2_bits(__floats2half2_rn(v1.z, v1.w));
        sts128(conv_sts, h0, h1, h2, h3);
    }

    for (int kcc = 0; kcc < KCHUNKS; ++kcc) {
        cp_wait1();
        __syncthreads();

        if (kcc + 1 < KCHUNKS) {
            const uint32_t src = conv_lds + ((kcc + 1) & (STAGES - 1)) * ST_BYTES;
            float4 v0, v1;
            lds128(v0, src);
            lds128(v1, src + 16);
            uint32_t h0 = half2_bits(__floats2half2_rn(v0.x, v0.y));
            uint32_t h1 = half2_bits(__floats2half2_rn(v0.z, v0.w));
            uint32_t h2 = half2_bits(__floats2half2_rn(v1.x, v1.y));
            uint32_t h3 = half2_bits(__floats2half2_rn(v1.z, v1.w));
            sts128(conv_sts + ((kcc + 1) & 1) * A16_BUF_BYTES, h0, h1, h2, h3);
        }

        const int next = kcc + STAGES - 1;
        if (next < KCHUNKS) load_stage(next & (STAGES - 1), next, mt, nt, FM, smbase, tid);
        cp_commit();

        const uint32_t sa = smbase + A16_OFF + (kcc & 1) * A16_BUF_BYTES;
        const uint32_t sb = smbase + (kcc & (STAGES - 1)) * ST_BYTES + A32_ST_BYTES;

#pragma unroll
        for (int ks = 0; ks < 2; ++ks) {
            const int k0 = ks * 16;
            uint32_t a[2][4];
#pragma unroll
            for (int i = 0; i < 2; ++i) {
                int m    = warp_m * 32 + i * 16 + (lane & 15);
                int koff = k0 + ((lane >> 4) << 3);
                ldm_x4(a[i], sa + (uint32_t)m * (A16_PITCH * 2) + (uint32_t)koff * 2);
            }
            uint32_t b[8][2];
#pragma unroll
            for (int j2 = 0; j2 < 4; ++j2) {
                int k    = k0 + (lane & 15);
                int clog = ((warp_n * 64 + j2 * 16) >> 3) + (lane >> 4);
                uint32_t addr = sb + ((uint32_t)k * 32 + (uint32_t)(clog ^ (k & 7))) * 16;
                uint32_t r0, r1, r2, r3;
                ldm_x4_t(r0, r1, r2, r3, addr);
                b[j2 * 2][0]     = r0; b[j2 * 2][1]     = r1;
                b[j2 * 2 + 1][0] = r2; b[j2 * 2 + 1][1] = r3;
            }
#pragma unroll
            for (int i = 0; i < 2; ++i)
#pragma unroll
                for (int j = 0; j < 8; ++j)
                    mma_fp16(c[i][j], a[i], b[j]);
        }
    }

    __syncthreads();
    float* red = (float*)dynsmem;

    float b1v[8][2], w2a[8][2], w2b[8][2];
#pragma unroll
    for (int j = 0; j < 8; ++j)
#pragma unroll
        for (int cc = 0; cc < 2; ++cc) {
            int gn = nt * BN + warp_n * 64 + j * 8 + (lane & 3) * 2 + cc;
            b1v[j][cc] = b1[gn];
            w2a[j][cc] = W2[gn * 2 + 0];
            w2b[j][cc] = W2[gn * 2 + 1];
        }

#pragma unroll
    for (int i = 0; i < 2; ++i) {
#pragma unroll
        for (int rh = 0; rh < 2; ++rh) {
            float p0 = 0.f, p1 = 0.f;
#pragma unroll
            for (int j = 0; j < 8; ++j)
#pragma unroll
                for (int cc = 0; cc < 2; ++cc) {
                    float h = ftanh(c[i][j][rh * 2 + cc] + b1v[j][cc]);
                    p0 = fmaf(h, w2a[j][cc], p0);
                    p1 = fmaf(h, w2b[j][cc], p1);
                }
            int row  = warp_m * 32 + i * 16 + (lane >> 2) + rh * 8;
            int slot = warp_n * 4 + (lane & 3);
            red[(row * 2 + 0) * 16 + slot] = p0;
            red[(row * 2 + 1) * 16 + slot] = p1;
        }
    }
    __syncthreads();
    if (tid < 128) {
        int row = tid >> 1, out = tid & 1;
        float s = 0.f;
#pragma unroll
        for (int sl = 0; sl < 16; ++sl) s += red[(row * 2 + out) * 16 + sl];
        g_po[((size_t)(mt * BM + row)) * 4 + nt * 2 + out] = s;
    }
}

// ---------------------------------------------------------------------------
// HMM scan: three-tier visit processing with load prefetch.
// ---------------------------------------------------------------------------
__device__ __forceinline__ float lse2(float a, float b)
{
    float m = fmaxf(a, b);
    float d = fabsf(a - b);
    return m + log1pf(expf(-d));
}

struct ChainState {
    float lt00, lt01, lt10, lt11;
    float ol00, ol01, ol10, ol11;
    float la0, la1;
    float bb0, bb1;
};

__device__ __forceinline__ void bkt_step(uint32_t entry, float4 po, int b,
                                         ChainState& s, float* __restrict__ out)
{
    const int t = (int)(entry >> 1);
    const int y = (int)(entry & 1u);
    const size_t m = (size_t)(b * TLEN + t);
    float o0 = s.bb0 + po.x + po.z;
    float o1 = s.bb1 + po.y + po.w;

    float e00 = s.ol00 + o0, e01 = s.ol01 - o0;
    float l0  = lse2(e00, e01);
    float lo00 = e00 - l0, lo01 = e01 - l0;
    float e10 = s.ol10 + o1, e11 = s.ol11 - o1;
    float l1  = lse2(e10, e11);
    float lo10 = e10 - l1, lo11 = e11 - l1;

    float py0 = lse2(lo00 + s.la0, lo10 + s.la1);
    float py1 = lse2(lo01 + s.la0, lo11 + s.la1);
    float pn  = lse2(py0, py1);
    out[m * 2 + 0] = py0 - pn;
    out[m * 2 + 1] = py1 - pn;

    float lp0 = y ? lo01 : lo00;
    float lp1 = y ? lo11 : lo10;
    float na0 = lse2(lp0 + s.la0 + s.lt00, lp1 + s.la1 + s.lt01);
    float na1 = lse2(lp0 + s.la0 + s.lt10, lp1 + s.la1 + s.lt11);
    s.la0 = na0; s.la1 = na1;
}

__global__ __launch_bounds__(128)
void scan_kernel(const float* __restrict__ trans_logits,
                 const float* __restrict__ obs_logits,
                 const float* __restrict__ init_logits,
                 const float* __restrict__ b2,
                 float* __restrict__ out)
{
    const int b = blockIdx.x;
    const int c = blockIdx.y * 128 + threadIdx.x;
    if (c >= NK) return;

    const int vbase = g_vstart[b * (NKP + 1) + c];
    const int vend  = g_vstart[b * (NKP + 1) + c + 1];
    const int n     = vend - vbase;
    if (n == 0) return;

    ChainState s;
    {
        float t00 = trans_logits[c * 4 + 0];
        float t01 = trans_logits[c * 4 + 1];
        float t10 = trans_logits[c * 4 + 2];
        float t11 = trans_logits[c * 4 + 3];
        float ls0 = lse2(t00, t10);
        float ls1 = lse2(t01, t11);
        s.lt00 = t00 - ls0; s.lt10 = t10 - ls0;
        s.lt01 = t01 - ls1; s.lt11 = t11 - ls1;

        float i0 = init_logits[c * 2 + 0];
        float i1 = init_logits[c * 2 + 1];
        float li = lse2(i0, i1);
        s.la0 = i0 - li; s.la1 = i1 - li;

        s.ol00 = obs_logits[c * 4 + 0];
        s.ol01 = obs_logits[c * 4 + 1];
        s.ol10 = obs_logits[c * 4 + 2];
        s.ol11 = obs_logits[c * 4 + 3];
        s.bb0 = b2[0]; s.bb1 = b2[1];
    }

    const uint32_t* vis = &g_visits[b * TLEN + vbase];

    if (n <= VIS_FAST) {
        // tier 1: sort in registers, prefetch ALL po loads (MLP = n)
        uint32_t e[VIS_FAST];
#pragma unroll
        for (int j = 0; j < VIS_FAST; ++j)
            e[j] = (j < n) ? vis[j] : 0xFFFFFFFFu;

        uint32_t ord[VIS_FAST];
        uint32_t last = 0;
#pragma unroll
        for (int i = 0; i < VIS_FAST; ++i) {
            uint32_t best = 0xFFFFFFFFu;
#pragma unroll
            for (int j = 0; j < VIS_FAST; ++j) {
                uint32_t ej = e[j];
                bool ok = (i == 0) ? (ej < best) : (ej > last && ej < best);
                if (ok) best = ej;
            }
            ord[i] = best;
            last = best;
        }

        float4 po[VIS_FAST];
#pragma unroll
        for (int i = 0; i < VIS_FAST; ++i)
            if (i < n)
                po[i] = *(const float4*)&g_po[((size_t)(b * TLEN + (int)(ord[i] >> 1))) * 4];

#pragma unroll
        for (int i = 0; i < VIS_FAST; ++i)
            if (i < n)
                bkt_step(ord[i], po[i], b, s, out);
    } else if (n <= VIS_CAP) {
        // tier 2: register cache + depth-2 load pipeline
        uint32_t e[VIS_CAP];
#pragma unroll
        for (int j = 0; j < VIS_CAP; ++j)
            e[j] = (j < n) ? vis[j] : 0xFFFFFFFFu;

        // first entry
        uint32_t cur = 0xFFFFFFFFu;
#pragma unroll
        for (int j = 0; j < VIS_CAP; ++j)
            if (e[j] < cur) cur = e[j];
        float4 po_cur = *(const float4*)&g_po[((size_t)(b * TLEN + (int)(cur >> 1))) * 4];

        for (int i = 0; i < n; ++i) {
            uint32_t nxt = 0xFFFFFFFFu;
            if (i + 1 < n) {
#pragma unroll
                for (int j = 0; j < VIS_CAP; ++j) {
                    uint32_t ej = e[j];
                    if (ej > cur && ej < nxt) nxt = ej;
                }
            }
            float4 po_nxt = make_float4(0.f, 0.f, 0.f, 0.f);
            if (i + 1 < n)
                po_nxt = *(const float4*)&g_po[((size_t)(b * TLEN + (int)(nxt >> 1))) * 4];

            bkt_step(cur, po_cur, b, s, out);
            cur = nxt; po_cur = po_nxt;
        }
    } else {
        // tier 3: gmem fallback
        uint32_t last = 0;
        for (int i = 0; i < n; ++i) {
            uint32_t best = 0xFFFFFFFFu;
            for (int j = 0; j < n; ++j) {
                uint32_t ej = vis[j];
                if ((i == 0 || ej > last) && ej < best) best = ej;
            }
            last = best;
            float4 po = *(const float4*)&g_po[((size_t)(b * TLEN + (int)(best >> 1))) * 4];
            bkt_step(best, po, b, s, out);
        }
    }
}

// ---------------------------------------------------------------------------
// Launch
// ---------------------------------------------------------------------------
extern "C" void kernel_launch(void* const* d_in, const int* in_sizes, int n_in,
                              void* d_out, int out_size)
{
    const int*   corr = (const int*)  d_in[0];
    const int*   kc   = (const int*)  d_in[1];
    const float* FM   = (const float*)d_in[2];
    const float* W1   = (const float*)d_in[3];
    const float* b1   = (const float*)d_in[4];
    const float* W2   = (const float*)d_in[5];
    const float* b2   = (const float*)d_in[6];
    const float* trl  = (const float*)d_in[7];
    const float* obl  = (const float*)d_in[8];
    const float* inl  = (const float*)d_in[9];
    float* out = (float*)d_out;

    static bool attr_set = false;
    if (!attr_set) {
        cudaFuncSetAttribute(gemm_hmma,
                             cudaFuncAttributeMaxDynamicSharedMemorySize, DYN_SMEM);
        attr_set = true;
    }

    prep_kernel<<<BATCH + 128, 512>>>(W1, corr, kc);

    gemm_hmma<<<dim3(2, MROWS / BM), 256, DYN_SMEM>>>(FM, b1, W2);

    scan_kernel<<<dim3(BATCH, 4), 128>>>(trl, obl, inl, b2, out);
}